// round 15
// baseline (speedup 1.0000x reference)
#include <cuda_runtime.h>

#define HH 512
#define WW 512
#define NCHUNK 64
#define RPC (HH / NCHUNK)   // 8 rows per block -> grid 4096, fine-grain tail

__device__ __forceinline__ int rrow(int r) {
    return r < 0 ? -r : (r >= HH ? 2 * HH - 2 - r : r);
}

__device__ __forceinline__ float med3(float a, float b, float c) {
    return fmaxf(fminf(a, b), fminf(fmaxf(a, b), c));
}

// insert a into sorted pair (p <= q) -> sorted triple (4 ops)
__device__ __forceinline__ void ins3(float a, float p, float q,
                                     float& lo, float& mi, float& hi) {
    lo = fminf(a, p);
    hi = fmaxf(a, q);
    mi = fmaxf(p, fminf(a, q));
}

// one output row: shuffles + boundary fixups + pair-shared combines + store
__device__ __forceinline__ void emit_row(
    const float tl0, const float tm0, const float th0,
    const float tl1, const float tm1, const float th1,
    const float tl2, const float tm2, const float th2,
    const float tl3, const float tm3, const float th3,
    const float tel, const float tem, const float teh,
    int lane, int stripe, float* __restrict__ orow) {

    float Ll = __shfl_up_sync(0xffffffffu, tl3, 1);
    float Lm = __shfl_up_sync(0xffffffffu, tm3, 1);
    float Lh = __shfl_up_sync(0xffffffffu, th3, 1);
    float Rl = __shfl_down_sync(0xffffffffu, tl0, 1);
    float Rm = __shfl_down_sync(0xffffffffu, tm0, 1);
    float Rh = __shfl_down_sync(0xffffffffu, th0, 1);
    if (lane == 0) {
        if (stripe > 0) { Ll = tel; Lm = tem; Lh = teh; }
        else            { Ll = tl1; Lm = tm1; Lh = th1; }   // reflect col -1 -> 1
    }
    if (lane == 31) {
        if (stripe < 3) { Rl = tel; Rm = tem; Rh = teh; }
        else            { Rl = tl2; Rm = tm2; Rh = th2; }   // reflect col 512 -> 510
    }

    // --- pair-shared combine ---
    float ul01 = fmaxf(tl0, tl1);
    float ul23 = fmaxf(tl2, tl3);
    float Ax = fmaxf(ul01, Ll);
    float Ay = fmaxf(ul01, tl2);
    float Az = fmaxf(ul23, tl1);
    float Aw = fmaxf(ul23, Rl);

    float vh01 = fminf(th0, th1);
    float vh23 = fminf(th2, th3);
    float Cx = fminf(vh01, Lh);
    float Cy = fminf(vh01, th2);
    float Cz = fminf(vh23, th1);
    float Cw = fminf(vh23, Rh);

    float mn01 = fminf(tm0, tm1), mx01 = fmaxf(tm0, tm1);
    float mn23 = fminf(tm2, tm3), mx23 = fmaxf(tm2, tm3);
    float Bx = fmaxf(mn01, fminf(mx01, Lm));
    float By = fmaxf(mn01, fminf(mx01, tm2));
    float Bz = fmaxf(mn23, fminf(mx23, tm1));
    float Bw = fmaxf(mn23, fminf(mx23, Rm));

    float4 o;
    o.x = med3(Ax, Bx, Cx);
    o.y = med3(Ay, By, Cy);
    o.z = med3(Az, Bz, Cz);
    o.w = med3(Aw, Bw, Cw);
    *(float4*)orow = o;
}

// One double-row step: loads rows k+2,k+3, emits output rows k,k+1, slides window.
template<bool INTERIOR>
__device__ __forceinline__ void step2(
    const float* __restrict__ base, const float* __restrict__ prow,
    const float* __restrict__ erow, float* __restrict__ orow,
    const int y0, const int k, const int c0, const int xe,
    const bool edge, const int lane, const int stripe,
    float4& a4, float4& b4, float4& c4,
    float& ae, float& be, float& ce) {

    float4 d4, n4;
    float de = 0.f, ne = 0.f;
    if (INTERIOR) {
        d4 = __ldg((const float4*)(prow + (k + 2) * WW));
        n4 = __ldg((const float4*)(prow + (k + 3) * WW));
        if (edge) {
            de = __ldg(erow + (k + 2) * WW);
            ne = __ldg(erow + (k + 3) * WW);
        }
    } else {
        const int y2 = rrow(y0 + k + 2);
        const int y3 = rrow(y0 + k + 3);
        d4 = __ldg((const float4*)(base + (size_t)y2 * WW + c0));
        n4 = __ldg((const float4*)(base + (size_t)y3 * WW + c0));
        if (edge) {
            de = __ldg(base + (size_t)y2 * WW + xe);
            ne = __ldg(base + (size_t)y3 * WW + xe);
        }
    }

    // Sorted pair of the two shared rows, per column
    float p0 = fminf(b4.x, c4.x), q0 = fmaxf(b4.x, c4.x);
    float p1 = fminf(b4.y, c4.y), q1 = fmaxf(b4.y, c4.y);
    float p2 = fminf(b4.z, c4.z), q2 = fmaxf(b4.z, c4.z);
    float p3 = fminf(b4.w, c4.w), q3 = fmaxf(b4.w, c4.w);
    float pe = fminf(be, ce),     qe = fmaxf(be, ce);

    // ---- output row y0+k: insert row above (a) ----
    {
        float l0,m0,h0,l1,m1,h1,l2,m2,h2,l3,m3,h3,le,me,he;
        ins3(a4.x, p0, q0, l0, m0, h0);
        ins3(a4.y, p1, q1, l1, m1, h1);
        ins3(a4.z, p2, q2, l2, m2, h2);
        ins3(a4.w, p3, q3, l3, m3, h3);
        ins3(ae,   pe, qe, le, me, he);
        emit_row(l0,m0,h0, l1,m1,h1, l2,m2,h2, l3,m3,h3, le,me,he,
                 lane, stripe, orow + k * WW);
    }

    // ---- output row y0+k+1: insert row below (d) ----
    {
        float l0,m0,h0,l1,m1,h1,l2,m2,h2,l3,m3,h3,le,me,he;
        ins3(d4.x, p0, q0, l0, m0, h0);
        ins3(d4.y, p1, q1, l1, m1, h1);
        ins3(d4.z, p2, q2, l2, m2, h2);
        ins3(d4.w, p3, q3, l3, m3, h3);
        ins3(de,   pe, qe, le, me, he);
        emit_row(l0,m0,h0, l1,m1,h1, l2,m2,h2, l3,m3,h3, le,me,he,
                 lane, stripe, orow + (k + 1) * WW);
    }

    // slide window down by 2 (renamed away under full unroll)
    a4 = c4; b4 = d4; c4 = n4;
    ae = ce; be = de; ce = ne;
}

// Chunk body. INTERIOR=true: no reflection possible -> compile-time row offsets,
// fully unrolled, branch- and IMAD-free addressing.
template<bool INTERIOR>
__device__ __forceinline__ void median_chunk(
    const float* __restrict__ base, float* __restrict__ obase,
    const int lane, const int stripe, const int y0) {

    const int c0 = stripe * 128 + lane * 4;
    const bool edge = (lane == 0 && stripe > 0) || (lane == 31 && stripe < 3);
    const int  xe   = (lane == 0) ? (c0 - 1) : (c0 + 4);

    const float* __restrict__ prow = base  + (size_t)y0 * WW + c0;   // row y0, main cols
    const float* __restrict__ erow = base  + (size_t)y0 * WW + xe;   // row y0, edge col
    float* __restrict__       orow = obase + (size_t)y0 * WW + c0;

    float4 a4, b4, c4;
    float ae = 0.f, be = 0.f, ce = 0.f;
    if (INTERIOR) {
        a4 = __ldg((const float4*)(prow - WW));
        b4 = __ldg((const float4*)(prow));
        c4 = __ldg((const float4*)(prow + WW));
        if (edge) {
            ae = __ldg(erow - WW);
            be = __ldg(erow);
            ce = __ldg(erow + WW);
        }
    } else {
        const int ym = rrow(y0 - 1);
        const int yp = rrow(y0 + 1);
        a4 = __ldg((const float4*)(base + (size_t)ym * WW + c0));
        b4 = __ldg((const float4*)(base + (size_t)y0 * WW + c0));
        c4 = __ldg((const float4*)(base + (size_t)yp * WW + c0));
        if (edge) {
            ae = __ldg(base + (size_t)ym * WW + xe);
            be = __ldg(base + (size_t)y0 * WW + xe);
            ce = __ldg(base + (size_t)yp * WW + xe);
        }
    }

    if (INTERIOR) {
#pragma unroll 4
        for (int k = 0; k < RPC; k += 2)
            step2<true>(base, prow, erow, orow, y0, k, c0, xe, edge, lane, stripe,
                        a4, b4, c4, ae, be, ce);
    } else {
#pragma unroll 2
        for (int k = 0; k < RPC; k += 2)
            step2<false>(base, prow, erow, orow, y0, k, c0, xe, edge, lane, stripe,
                         a4, b4, c4, ae, be, ce);
    }
}

__global__ __launch_bounds__(128, 8)
void median3x3_kernel(const float* __restrict__ x, float* __restrict__ out) {
    const int lane   = threadIdx.x & 31;
    const int stripe = threadIdx.x >> 5;   // 0..3, each warp owns 128 columns
    const int img    = blockIdx.y;
    const int chunk  = blockIdx.x;

    const float* __restrict__ base  = x   + (size_t)img * HH * WW;
    float* __restrict__       obase = out + (size_t)img * HH * WW;
    const int y0 = chunk * RPC;

    if (chunk > 0 && chunk < NCHUNK - 1) {
        median_chunk<true>(base, obase, lane, stripe, y0);
    } else {
        median_chunk<false>(base, obase, lane, stripe, y0);
    }
}

extern "C" void kernel_launch(void* const* d_in, const int* in_sizes, int n_in,
                              void* d_out, int out_size) {
    const float* x = (const float*)d_in[0];
    float* out = (float*)d_out;
    const int nimg = in_sizes[0] / (HH * WW);   // 64 for [8,8,512,512]
    dim3 grid(NCHUNK, nimg);
    median3x3_kernel<<<grid, 128>>>(x, out);
}

// round 16
// speedup vs baseline: 1.3156x; 1.3156x over previous
#include <cuda_runtime.h>

#define HH 512
#define WW 512
#define NCHUNK 32
#define RPC (HH / NCHUNK)   // 16 rows per block -> grid 2048 (proven optimum)

__device__ __forceinline__ int rrow(int r) {
    return r < 0 ? -r : (r >= HH ? 2 * HH - 2 - r : r);
}

__device__ __forceinline__ float med3(float a, float b, float c) {
    return fmaxf(fminf(a, b), fminf(fmaxf(a, b), c));
}

// insert a into sorted pair (p <= q) -> sorted triple (4 ops)
__device__ __forceinline__ void ins3(float a, float p, float q,
                                     float& lo, float& mi, float& hi) {
    lo = fminf(a, p);
    hi = fmaxf(a, q);
    mi = fmaxf(p, fminf(a, q));
}

// streaming write-through store: output is never re-read; don't pollute L2
__device__ __forceinline__ void stwt4(float* p, float4 v) {
    asm volatile("st.global.wt.v4.f32 [%0], {%1, %2, %3, %4};"
                 :: "l"(p), "f"(v.x), "f"(v.y), "f"(v.z), "f"(v.w) : "memory");
}

// one output row: shuffles + boundary fixups + pair-shared combines + store
__device__ __forceinline__ void emit_row(
    const float tl0, const float tm0, const float th0,
    const float tl1, const float tm1, const float th1,
    const float tl2, const float tm2, const float th2,
    const float tl3, const float tm3, const float th3,
    const float tel, const float tem, const float teh,
    int lane, int stripe, float* __restrict__ orow) {

    float Ll = __shfl_up_sync(0xffffffffu, tl3, 1);
    float Lm = __shfl_up_sync(0xffffffffu, tm3, 1);
    float Lh = __shfl_up_sync(0xffffffffu, th3, 1);
    float Rl = __shfl_down_sync(0xffffffffu, tl0, 1);
    float Rm = __shfl_down_sync(0xffffffffu, tm0, 1);
    float Rh = __shfl_down_sync(0xffffffffu, th0, 1);
    if (lane == 0) {
        if (stripe > 0) { Ll = tel; Lm = tem; Lh = teh; }
        else            { Ll = tl1; Lm = tm1; Lh = th1; }   // reflect col -1 -> 1
    }
    if (lane == 31) {
        if (stripe < 3) { Rl = tel; Rm = tem; Rh = teh; }
        else            { Rl = tl2; Rm = tm2; Rh = th2; }   // reflect col 512 -> 510
    }

    // --- pair-shared combine ---
    float ul01 = fmaxf(tl0, tl1);
    float ul23 = fmaxf(tl2, tl3);
    float Ax = fmaxf(ul01, Ll);
    float Ay = fmaxf(ul01, tl2);
    float Az = fmaxf(ul23, tl1);
    float Aw = fmaxf(ul23, Rl);

    float vh01 = fminf(th0, th1);
    float vh23 = fminf(th2, th3);
    float Cx = fminf(vh01, Lh);
    float Cy = fminf(vh01, th2);
    float Cz = fminf(vh23, th1);
    float Cw = fminf(vh23, Rh);

    float mn01 = fminf(tm0, tm1), mx01 = fmaxf(tm0, tm1);
    float mn23 = fminf(tm2, tm3), mx23 = fmaxf(tm2, tm3);
    float Bx = fmaxf(mn01, fminf(mx01, Lm));
    float By = fmaxf(mn01, fminf(mx01, tm2));
    float Bz = fmaxf(mn23, fminf(mx23, tm1));
    float Bw = fmaxf(mn23, fminf(mx23, Rm));

    float4 o;
    o.x = med3(Ax, Bx, Cx);
    o.y = med3(Ay, By, Cy);
    o.z = med3(Az, Bz, Cz);
    o.w = med3(Aw, Bw, Cw);
    stwt4(orow, o);
}

// One double-row step: loads rows k+2,k+3, emits output rows k,k+1, slides window.
template<bool INTERIOR>
__device__ __forceinline__ void step2(
    const float* __restrict__ base, const float* __restrict__ prow,
    const float* __restrict__ erow, float* __restrict__ orow,
    const int y0, const int k, const int c0, const int xe,
    const bool edge, const int lane, const int stripe,
    float4& a4, float4& b4, float4& c4,
    float& ae, float& be, float& ce) {

    float4 d4, n4;
    float de = 0.f, ne = 0.f;
    if (INTERIOR) {
        d4 = __ldg((const float4*)(prow + (k + 2) * WW));
        n4 = __ldg((const float4*)(prow + (k + 3) * WW));
        if (edge) {
            de = __ldg(erow + (k + 2) * WW);
            ne = __ldg(erow + (k + 3) * WW);
        }
    } else {
        const int y2 = rrow(y0 + k + 2);
        const int y3 = rrow(y0 + k + 3);
        d4 = __ldg((const float4*)(base + (size_t)y2 * WW + c0));
        n4 = __ldg((const float4*)(base + (size_t)y3 * WW + c0));
        if (edge) {
            de = __ldg(base + (size_t)y2 * WW + xe);
            ne = __ldg(base + (size_t)y3 * WW + xe);
        }
    }

    // Sorted pair of the two shared rows, per column
    float p0 = fminf(b4.x, c4.x), q0 = fmaxf(b4.x, c4.x);
    float p1 = fminf(b4.y, c4.y), q1 = fmaxf(b4.y, c4.y);
    float p2 = fminf(b4.z, c4.z), q2 = fmaxf(b4.z, c4.z);
    float p3 = fminf(b4.w, c4.w), q3 = fmaxf(b4.w, c4.w);
    float pe = fminf(be, ce),     qe = fmaxf(be, ce);

    // ---- output row y0+k: insert row above (a) ----
    {
        float l0,m0,h0,l1,m1,h1,l2,m2,h2,l3,m3,h3,le,me,he;
        ins3(a4.x, p0, q0, l0, m0, h0);
        ins3(a4.y, p1, q1, l1, m1, h1);
        ins3(a4.z, p2, q2, l2, m2, h2);
        ins3(a4.w, p3, q3, l3, m3, h3);
        ins3(ae,   pe, qe, le, me, he);
        emit_row(l0,m0,h0, l1,m1,h1, l2,m2,h2, l3,m3,h3, le,me,he,
                 lane, stripe, orow + k * WW);
    }

    // ---- output row y0+k+1: insert row below (d) ----
    {
        float l0,m0,h0,l1,m1,h1,l2,m2,h2,l3,m3,h3,le,me,he;
        ins3(d4.x, p0, q0, l0, m0, h0);
        ins3(d4.y, p1, q1, l1, m1, h1);
        ins3(d4.z, p2, q2, l2, m2, h2);
        ins3(d4.w, p3, q3, l3, m3, h3);
        ins3(de,   pe, qe, le, me, he);
        emit_row(l0,m0,h0, l1,m1,h1, l2,m2,h2, l3,m3,h3, le,me,he,
                 lane, stripe, orow + (k + 1) * WW);
    }

    // slide window down by 2 (renamed away under full unroll)
    a4 = c4; b4 = d4; c4 = n4;
    ae = ce; be = de; ce = ne;
}

// Chunk body. INTERIOR=true: no reflection possible -> compile-time row offsets,
// fully unrolled, branch- and IMAD-free addressing.
template<bool INTERIOR>
__device__ __forceinline__ void median_chunk(
    const float* __restrict__ base, float* __restrict__ obase,
    const int lane, const int stripe, const int y0) {

    const int c0 = stripe * 128 + lane * 4;
    const bool edge = (lane == 0 && stripe > 0) || (lane == 31 && stripe < 3);
    const int  xe   = (lane == 0) ? (c0 - 1) : (c0 + 4);

    const float* __restrict__ prow = base  + (size_t)y0 * WW + c0;   // row y0, main cols
    const float* __restrict__ erow = base  + (size_t)y0 * WW + xe;   // row y0, edge col
    float* __restrict__       orow = obase + (size_t)y0 * WW + c0;

    float4 a4, b4, c4;
    float ae = 0.f, be = 0.f, ce = 0.f;
    if (INTERIOR) {
        a4 = __ldg((const float4*)(prow - WW));
        b4 = __ldg((const float4*)(prow));
        c4 = __ldg((const float4*)(prow + WW));
        if (edge) {
            ae = __ldg(erow - WW);
            be = __ldg(erow);
            ce = __ldg(erow + WW);
        }
    } else {
        const int ym = rrow(y0 - 1);
        const int yp = rrow(y0 + 1);
        a4 = __ldg((const float4*)(base + (size_t)ym * WW + c0));
        b4 = __ldg((const float4*)(base + (size_t)y0 * WW + c0));
        c4 = __ldg((const float4*)(base + (size_t)yp * WW + c0));
        if (edge) {
            ae = __ldg(base + (size_t)ym * WW + xe);
            be = __ldg(base + (size_t)y0 * WW + xe);
            ce = __ldg(base + (size_t)yp * WW + xe);
        }
    }

    if (INTERIOR) {
#pragma unroll 8
        for (int k = 0; k < RPC; k += 2)
            step2<true>(base, prow, erow, orow, y0, k, c0, xe, edge, lane, stripe,
                        a4, b4, c4, ae, be, ce);
    } else {
#pragma unroll 2
        for (int k = 0; k < RPC; k += 2)
            step2<false>(base, prow, erow, orow, y0, k, c0, xe, edge, lane, stripe,
                         a4, b4, c4, ae, be, ce);
    }
}

__global__ __launch_bounds__(128, 8)
void median3x3_kernel(const float* __restrict__ x, float* __restrict__ out) {
    const int lane   = threadIdx.x & 31;
    const int stripe = threadIdx.x >> 5;   // 0..3, each warp owns 128 columns
    const int img    = blockIdx.y;
    const int chunk  = blockIdx.x;

    const float* __restrict__ base  = x   + (size_t)img * HH * WW;
    float* __restrict__       obase = out + (size_t)img * HH * WW;
    const int y0 = chunk * RPC;

    if (chunk > 0 && chunk < NCHUNK - 1) {
        median_chunk<true>(base, obase, lane, stripe, y0);
    } else {
        median_chunk<false>(base, obase, lane, stripe, y0);
    }
}

extern "C" void kernel_launch(void* const* d_in, const int* in_sizes, int n_in,
                              void* d_out, int out_size) {
    const float* x = (const float*)d_in[0];
    float* out = (float*)d_out;
    const int nimg = in_sizes[0] / (HH * WW);   // 64 for [8,8,512,512]
    dim3 grid(NCHUNK, nimg);
    median3x3_kernel<<<grid, 128>>>(x, out);
}